// round 7
// baseline (speedup 1.0000x reference)
#include <cuda_runtime.h>
#include <cuda_fp16.h>
#include <mma.h>
#include <math.h>
#include <stdint.h>

using namespace nvcuda;

// Problem constants
#define NN 50000
#define NE 800000
#define NF 128
#define NH 128
#define NH2 64
#define NG 512

// ---------------- scratch (static device globals; no allocation) -------------
__device__ __half d_g[(size_t)NN * NF]; // dinv-scaled projected features (fp16)
__device__ float  d_h[(size_t)NN * NF]; // activations (fp32)
__device__ float  d_dinv[NN];
__device__ int    d_cnt[NN];
__device__ int    d_rowptr[NN + 1];
__device__ int    d_cursor[NN];
__device__ int    d_col[NE];
__device__ float  d_pool[NG * NH2];
__device__ int    d_gcnt[NG];

// ---------------- init ------------------------------------------------------
__global__ void init_kernel() {
    int i = blockIdx.x * blockDim.x + threadIdx.x;
    if (i < NN) d_cnt[i] = 0;
    if (i < NG * NH2) d_pool[i] = 0.0f;
    if (i < NG) d_gcnt[i] = 0;
}

// ---------------- degree count (real edges only; self-loop is +1 implicit) --
__global__ void count_kernel(const int* __restrict__ ei) {
    int e = blockIdx.x * blockDim.x + threadIdx.x;
    if (e < NE) {
        int dst = ei[NE + e];
        atomicAdd(&d_cnt[dst], 1);
    }
}

// ---------------- single-block scan: rowptr/cursor/dinv ----------------------
__global__ void scan_kernel() {
    __shared__ int warp_sums[32];
    __shared__ int s_carry;
    int tid = threadIdx.x, lane = tid & 31, wid = tid >> 5;
    if (tid == 0) s_carry = 0;
    __syncthreads();
    for (int base = 0; base < NN; base += 1024) {
        int i = base + tid;
        int v = (i < NN) ? d_cnt[i] : 0;
        int x = v;
        #pragma unroll
        for (int o = 1; o < 32; o <<= 1) {
            int t = __shfl_up_sync(0xFFFFFFFFu, x, o);
            if (lane >= o) x += t;
        }
        if (lane == 31) warp_sums[wid] = x;
        __syncthreads();
        if (wid == 0) {
            int w = warp_sums[lane];
            #pragma unroll
            for (int o = 1; o < 32; o <<= 1) {
                int t = __shfl_up_sync(0xFFFFFFFFu, w, o);
                if (lane >= o) w += t;
            }
            warp_sums[lane] = w;
        }
        __syncthreads();
        int warp_prefix = (wid > 0) ? warp_sums[wid - 1] : 0;
        int incl = s_carry + warp_prefix + x;
        int excl = incl - v;
        if (i < NN) {
            d_rowptr[i] = excl;
            d_cursor[i] = excl;
            d_dinv[i]   = rsqrtf((float)(v + 1));  // deg includes self-loop, >= 1
        }
        __syncthreads();
        if (tid == 1023) s_carry = incl;
        __syncthreads();
    }
    if (threadIdx.x == 0) d_rowptr[NN] = s_carry;
}

// ---------------- CSR fill ---------------------------------------------------
__global__ void fill_kernel(const int* __restrict__ ei) {
    int e = blockIdx.x * blockDim.x + threadIdx.x;
    if (e < NE) {
        int s = ei[e];
        int d = ei[NE + e];
        int p = atomicAdd(&d_cursor[d], 1);
        d_col[p] = s;
    }
}

// ---------------- tf32 tensor GEMM: d_g = half( dinv[row] * (A @ W) ) --------
// 256 threads = 8 warps; block tile 128 x N; warp = 16-row strip, N/16 frags.
template <int K, int N, int SRC>   // SRC 0: A = param (x), 1: A = d_h
__global__ void gemm_tc_kernel(const float* __restrict__ Aparam,
                               const float* __restrict__ W, int M) {
    constexpr int NFRAG = N / 16;
    __shared__ float Ws[8][N];          // tf32-rounded W k-slice
    __shared__ float Astage[8][16 * 8]; // boundary-block A staging (per warp)
    __shared__ float Cs[8][16 * 20];    // epilogue bounce (ld=20, per warp)

    const float* __restrict__ A = (SRC == 0) ? Aparam : d_h;
    int tid = threadIdx.x, warp = tid >> 5, lane = tid & 31;
    int m0 = blockIdx.x * 128;
    int mrow = m0 + warp * 16;
    bool full = (mrow + 16 <= M);

    wmma::fragment<wmma::accumulator, 16, 16, 8, float> acc[NFRAG];
    #pragma unroll
    for (int nf = 0; nf < NFRAG; nf++) wmma::fill_fragment(acc[nf], 0.0f);

    for (int k0 = 0; k0 < K; k0 += 8) {
        // stage W slice, pre-rounded to tf32
        for (int idx = tid; idx < 8 * N; idx += 256) {
            int r = idx / N, c = idx % N;
            Ws[r][c] = wmma::__float_to_tf32(W[(k0 + r) * N + c]);
        }
        __syncthreads();

        wmma::fragment<wmma::matrix_a, 16, 16, 8, wmma::precision::tf32, wmma::row_major> a;
        if (full) {
            wmma::load_matrix_sync(a, A + (size_t)mrow * K + k0, K);
        } else {
            // bounds-checked staging for the partial boundary block
            for (int idx = lane; idx < 16 * 8; idx += 32) {
                int r = idx >> 3, c = idx & 7;
                int row = mrow + r;
                Astage[warp][r * 8 + c] =
                    (row < M) ? A[(size_t)row * K + k0 + c] : 0.0f;
            }
            __syncwarp();
            wmma::load_matrix_sync(a, Astage[warp], 8);
        }
        #pragma unroll
        for (int i = 0; i < a.num_elements; i++)
            a.x[i] = wmma::__float_to_tf32(a.x[i]);

        #pragma unroll
        for (int nf = 0; nf < NFRAG; nf++) {
            wmma::fragment<wmma::matrix_b, 16, 16, 8, wmma::precision::tf32, wmma::row_major> b;
            wmma::load_matrix_sync(b, &Ws[0][nf * 16], N);
            wmma::mma_sync(acc[nf], a, b, acc[nf]);
        }
        __syncthreads();
    }

    // epilogue: bounce each 16x16 frag through smem, scale by dinv, fp16 store
    int r = lane >> 1;
    int c0 = (lane & 1) * 8;
    int row = mrow + r;
    float s = (row < M) ? d_dinv[row] : 0.0f;
    #pragma unroll
    for (int nf = 0; nf < NFRAG; nf++) {
        wmma::store_matrix_sync(&Cs[warp][0], acc[nf], 20, wmma::mem_row_major);
        __syncwarp();
        if (row < M) {
            float v[8];
            #pragma unroll
            for (int j = 0; j < 8; j++) v[j] = Cs[warp][r * 20 + c0 + j] * s;
            __half2 h[4];
            #pragma unroll
            for (int j = 0; j < 4; j++)
                h[j] = __floats2half2_rn(v[2 * j], v[2 * j + 1]);
            *(uint4*)&d_g[(size_t)row * N + nf * 16 + c0] = *(uint4*)h;
        }
        __syncwarp();
    }
}

// ---------------- aggregation: out[i] = act(dinv[i]*(self + sum g[src]) + b) -
// block per node, F threads; g is fp16, accumulate fp32.
// MODE 0: relu -> d_h ;  MODE 2: no relu, fused pooling atomics
template <int F, int MODE>
__global__ void agg_kernel(const float* __restrict__ bias,
                           const int* __restrict__ batch) {
    int i = blockIdx.x;
    int f = threadIdx.x;
    float acc = __half2float(d_g[(size_t)i * F + f]);   // self-loop term
    int s = d_rowptr[i], e = d_rowptr[i + 1];
    int k = s;
    for (; k + 4 <= e; k += 4) {
        int c0 = d_col[k + 0];
        int c1 = d_col[k + 1];
        int c2 = d_col[k + 2];
        int c3 = d_col[k + 3];
        acc += __half2float(d_g[(size_t)c0 * F + f]);
        acc += __half2float(d_g[(size_t)c1 * F + f]);
        acc += __half2float(d_g[(size_t)c2 * F + f]);
        acc += __half2float(d_g[(size_t)c3 * F + f]);
    }
    for (; k < e; k++) acc += __half2float(d_g[(size_t)d_col[k] * F + f]);
    float v = d_dinv[i] * acc + bias[f];
    if (MODE == 0) {
        d_h[(size_t)i * F + f] = fmaxf(v, 0.0f);
    } else {
        int b = batch[i];
        atomicAdd(&d_pool[b * NH2 + f], v);
        if (f == 0) atomicAdd(&d_gcnt[b], 1);
    }
}

// ---------------- final: sigmoid(mean) @ Wfc + bfc ---------------------------
__global__ void final_kernel(const float* __restrict__ Wfc,
                             const float* __restrict__ bfc,
                             float* __restrict__ out) {
    int gidx = blockIdx.x * (blockDim.x >> 5) + (threadIdx.x >> 5);
    int lane = threadIdx.x & 31;
    if (gidx >= NG) return;
    float cnt = fmaxf((float)d_gcnt[gidx], 1.0f);
    float s0 = d_pool[gidx * NH2 + lane];
    float s1 = d_pool[gidx * NH2 + 32 + lane];
    float z0 = 1.0f / (1.0f + expf(-s0 / cnt));
    float z1 = 1.0f / (1.0f + expf(-s1 / cnt));
    float p = z0 * Wfc[lane] + z1 * Wfc[lane + 32];
    #pragma unroll
    for (int o = 16; o > 0; o >>= 1) p += __shfl_down_sync(0xFFFFFFFFu, p, o);
    if (lane == 0) out[gidx] = p + bfc[0];
}

// ---------------- launch -----------------------------------------------------
extern "C" void kernel_launch(void* const* d_in, const int* in_sizes, int n_in,
                              void* d_out, int out_size) {
    const float* x     = (const float*)d_in[0];
    const int*   ei    = (const int*)d_in[1];
    const int*   batch = (const int*)d_in[2];
    const float* W1    = (const float*)d_in[3];
    const float* b1    = (const float*)d_in[4];
    const float* W2    = (const float*)d_in[5];
    const float* b2    = (const float*)d_in[6];
    const float* W3    = (const float*)d_in[7];
    const float* b3    = (const float*)d_in[8];
    const float* Wfc   = (const float*)d_in[9];
    const float* bfc   = (const float*)d_in[10];
    float* out = (float*)d_out;

    const int gemm_blocks = (NN + 127) / 128;  // 391

    init_kernel<<<(NN + 255) / 256, 256>>>();
    count_kernel<<<(NE + 255) / 256, 256>>>(ei);
    scan_kernel<<<1, 1024>>>();
    fill_kernel<<<(NE + 255) / 256, 256>>>(ei);

    // layer 1: 128 -> 128, relu
    gemm_tc_kernel<128, 128, 0><<<gemm_blocks, 256>>>(x, W1, NN);
    agg_kernel<128, 0><<<NN, 128>>>(b1, batch);

    // layer 2: 128 -> 64, relu
    gemm_tc_kernel<128, 64, 1><<<gemm_blocks, 256>>>(nullptr, W2, NN);
    agg_kernel<64, 0><<<NN, 64>>>(b2, batch);

    // layer 3: 64 -> 64, no relu, fused pooling
    gemm_tc_kernel<64, 64, 1><<<gemm_blocks, 256>>>(nullptr, W3, NN);
    agg_kernel<64, 2><<<NN, 64>>>(b3, batch);

    final_kernel<<<(NG + 7) / 8, 256>>>(Wfc, bfc, out);
}

// round 8
// speedup vs baseline: 1.2253x; 1.2253x over previous
#include <cuda_runtime.h>
#include <cuda_fp16.h>
#include <math.h>
#include <stdint.h>

// Problem constants
#define NN 50000
#define NE 800000
#define NF 128
#define NH 128
#define NH2 64
#define NG 512

// ---------------- scratch (static device globals; no allocation) -------------
__device__ __half d_g[(size_t)NN * NF]; // dinv-scaled projected features (fp16)
__device__ float  d_h[(size_t)NN * NF]; // activations (fp32)
__device__ float  d_dinv[NN];
__device__ int    d_cnt[NN];
__device__ int    d_rowptr[NN + 1];
__device__ int    d_cursor[NN];
__device__ int    d_col[NE];
__device__ float  d_pool[NG * NH2];
__device__ int    d_gcnt[NG];

// ---------------- init ------------------------------------------------------
__global__ void init_kernel() {
    int i = blockIdx.x * blockDim.x + threadIdx.x;
    if (i < NN) d_cnt[i] = 0;
    if (i < NG * NH2) d_pool[i] = 0.0f;
    if (i < NG) d_gcnt[i] = 0;
}

// ---------------- degree count (real edges only; self-loop is +1 implicit) --
__global__ void count_kernel(const int* __restrict__ ei) {
    int e = blockIdx.x * blockDim.x + threadIdx.x;
    if (e < NE) {
        int dst = ei[NE + e];
        atomicAdd(&d_cnt[dst], 1);
    }
}

// ---------------- single-block scan: rowptr/cursor/dinv ----------------------
__global__ void scan_kernel() {
    __shared__ int warp_sums[32];
    __shared__ int s_carry;
    int tid = threadIdx.x, lane = tid & 31, wid = tid >> 5;
    if (tid == 0) s_carry = 0;
    __syncthreads();
    for (int base = 0; base < NN; base += 1024) {
        int i = base + tid;
        int v = (i < NN) ? d_cnt[i] : 0;
        int x = v;
        #pragma unroll
        for (int o = 1; o < 32; o <<= 1) {
            int t = __shfl_up_sync(0xFFFFFFFFu, x, o);
            if (lane >= o) x += t;
        }
        if (lane == 31) warp_sums[wid] = x;
        __syncthreads();
        if (wid == 0) {
            int w = warp_sums[lane];
            #pragma unroll
            for (int o = 1; o < 32; o <<= 1) {
                int t = __shfl_up_sync(0xFFFFFFFFu, w, o);
                if (lane >= o) w += t;
            }
            warp_sums[lane] = w;
        }
        __syncthreads();
        int warp_prefix = (wid > 0) ? warp_sums[wid - 1] : 0;
        int incl = s_carry + warp_prefix + x;
        int excl = incl - v;
        if (i < NN) {
            d_rowptr[i] = excl;
            d_cursor[i] = excl;
            d_dinv[i]   = rsqrtf((float)(v + 1));  // deg includes self-loop, >= 1
        }
        __syncthreads();
        if (tid == 1023) s_carry = incl;
        __syncthreads();
    }
    if (threadIdx.x == 0) d_rowptr[NN] = s_carry;
}

// ---------------- CSR fill ---------------------------------------------------
__global__ void fill_kernel(const int* __restrict__ ei) {
    int e = blockIdx.x * blockDim.x + threadIdx.x;
    if (e < NE) {
        int s = ei[e];
        int d = ei[NE + e];
        int p = atomicAdd(&d_cursor[d], 1);
        d_col[p] = s;
    }
}

// ---------------- GEMM: d_g = half( dinv[row] * (A @ W) ) --------------------
// BM=128, BK=8, 256 threads, per-thread 8 x (N/16)
template <int K, int N, int SRC>   // SRC 0: A = param (x), 1: A = d_h
__global__ void gemm_scale_kernel(const float* __restrict__ Aparam,
                                  const float* __restrict__ W, int M) {
    constexpr int TN = N / 16;
    __shared__ float As[8][128];
    __shared__ float Ws[8][N];
    const float* __restrict__ A = (SRC == 0) ? Aparam : d_h;

    int tid = threadIdx.x;
    int m0 = blockIdx.x * 128;
    int ty = tid >> 4, tx = tid & 15;
    int mb = ty * 8, nb = tx * TN;

    float acc[8][TN];
    #pragma unroll
    for (int i = 0; i < 8; i++)
        #pragma unroll
        for (int j = 0; j < TN; j++) acc[i][j] = 0.0f;

    int arow = tid >> 1;
    int ac = (tid & 1) * 4;
    bool aok = (m0 + arow) < M;
    const float* Ap = A + (size_t)(m0 + arow) * K + ac;

    for (int k0 = 0; k0 < K; k0 += 8) {
        float4 av = aok ? *(const float4*)(Ap + k0) : make_float4(0.f, 0.f, 0.f, 0.f);
        float4 wv = make_float4(0.f, 0.f, 0.f, 0.f);
        int wrow, wc;
        if (N == 128) {
            wrow = tid >> 5; wc = (tid & 31) * 4;
            wv = *(const float4*)&W[(k0 + wrow) * N + wc];
        } else {
            wrow = tid >> 4; wc = (tid & 15) * 4;
            if (tid < 128) wv = *(const float4*)&W[(k0 + wrow) * N + wc];
        }
        __syncthreads();
        As[ac + 0][arow] = av.x;
        As[ac + 1][arow] = av.y;
        As[ac + 2][arow] = av.z;
        As[ac + 3][arow] = av.w;
        if (N == 128 || tid < 128) *(float4*)&Ws[wrow][wc] = wv;
        __syncthreads();
        #pragma unroll
        for (int k = 0; k < 8; k++) {
            float a0[8];
            *(float4*)(a0)     = *(float4*)&As[k][mb];
            *(float4*)(a0 + 4) = *(float4*)&As[k][mb + 4];
            float b0[TN];
            #pragma unroll
            for (int j4 = 0; j4 < TN; j4 += 4)
                *(float4*)(b0 + j4) = *(float4*)&Ws[k][nb + j4];
            #pragma unroll
            for (int i = 0; i < 8; i++)
                #pragma unroll
                for (int j = 0; j < TN; j++)
                    acc[i][j] = fmaf(a0[i], b0[j], acc[i][j]);
        }
    }

    #pragma unroll
    for (int i = 0; i < 8; i++) {
        int row = m0 + mb + i;
        if (row < M) {
            float s = d_dinv[row];
            #pragma unroll
            for (int j4 = 0; j4 < TN; j4 += 4) {
                __half2 h0 = __floats2half2_rn(acc[i][j4 + 0] * s, acc[i][j4 + 1] * s);
                __half2 h1 = __floats2half2_rn(acc[i][j4 + 2] * s, acc[i][j4 + 3] * s);
                __half2* p = (__half2*)&d_g[(size_t)row * N + nb + j4];
                p[0] = h0;
                p[1] = h1;
            }
        }
    }
}

// ---------------- aggregation: out[i] = act(dinv[i]*(self + sum g[src]) + b) -
// block per node, F/2 threads; each thread owns 2 features via __half2.
// cols staged through smem (coalesced), gather loop unrolled 8 (MLP=8).
// MODE 0: relu -> d_h ;  MODE 2: no relu, fused pooling atomics
template <int F, int MODE>
__global__ void agg_kernel(const float* __restrict__ bias,
                           const int* __restrict__ batch) {
    constexpr int T = F / 2;   // threads per block
    __shared__ int scol[T];
    int i = blockIdx.x;
    int f = threadIdx.x;       // 0..T-1, owns features 2f, 2f+1
    const __half2* __restrict__ g2 = (const __half2*)d_g;

    __half2 h = g2[(size_t)i * T + f];          // self-loop term
    float2 acc;
    acc.x = __low2float(h);
    acc.y = __high2float(h);

    int s = d_rowptr[i], e = d_rowptr[i + 1];
    for (int base = s; base < e; base += T) {
        int n = min(T, e - base);
        __syncthreads();
        if (f < n) scol[f] = d_col[base + f];
        __syncthreads();
        int k = 0;
        for (; k + 8 <= n; k += 8) {
            #pragma unroll
            for (int j = 0; j < 8; j++) {
                int c = scol[k + j];
                __half2 v = g2[(size_t)c * T + f];
                acc.x += __low2float(v);
                acc.y += __high2float(v);
            }
        }
        for (; k < n; k++) {
            int c = scol[k];
            __half2 v = g2[(size_t)c * T + f];
            acc.x += __low2float(v);
            acc.y += __high2float(v);
        }
    }

    float di = d_dinv[i];
    float2 b2 = ((const float2*)bias)[f];
    float rx = fmaf(di, acc.x, b2.x);
    float ry = fmaf(di, acc.y, b2.y);
    if (MODE == 0) {
        float2 r;
        r.x = fmaxf(rx, 0.0f);
        r.y = fmaxf(ry, 0.0f);
        ((float2*)d_h)[(size_t)i * T + f] = r;
    } else {
        int b = batch[i];
        atomicAdd(&d_pool[b * NH2 + 2 * f + 0], rx);
        atomicAdd(&d_pool[b * NH2 + 2 * f + 1], ry);
        if (f == 0) atomicAdd(&d_gcnt[b], 1);
    }
}

// ---------------- final: sigmoid(mean) @ Wfc + bfc ---------------------------
__global__ void final_kernel(const float* __restrict__ Wfc,
                             const float* __restrict__ bfc,
                             float* __restrict__ out) {
    int gidx = blockIdx.x * (blockDim.x >> 5) + (threadIdx.x >> 5);
    int lane = threadIdx.x & 31;
    if (gidx >= NG) return;
    float cnt = fmaxf((float)d_gcnt[gidx], 1.0f);
    float s0 = d_pool[gidx * NH2 + lane];
    float s1 = d_pool[gidx * NH2 + 32 + lane];
    float z0 = 1.0f / (1.0f + expf(-s0 / cnt));
    float z1 = 1.0f / (1.0f + expf(-s1 / cnt));
    float p = z0 * Wfc[lane] + z1 * Wfc[lane + 32];
    #pragma unroll
    for (int o = 16; o > 0; o >>= 1) p += __shfl_down_sync(0xFFFFFFFFu, p, o);
    if (lane == 0) out[gidx] = p + bfc[0];
}

// ---------------- launch -----------------------------------------------------
extern "C" void kernel_launch(void* const* d_in, const int* in_sizes, int n_in,
                              void* d_out, int out_size) {
    const float* x     = (const float*)d_in[0];
    const int*   ei    = (const int*)d_in[1];
    const int*   batch = (const int*)d_in[2];
    const float* W1    = (const float*)d_in[3];
    const float* b1    = (const float*)d_in[4];
    const float* W2    = (const float*)d_in[5];
    const float* b2    = (const float*)d_in[6];
    const float* W3    = (const float*)d_in[7];
    const float* b3    = (const float*)d_in[8];
    const float* Wfc   = (const float*)d_in[9];
    const float* bfc   = (const float*)d_in[10];
    float* out = (float*)d_out;

    const int gemm_blocks = (NN + 127) / 128;  // 391

    init_kernel<<<(NN + 255) / 256, 256>>>();
    count_kernel<<<(NE + 255) / 256, 256>>>(ei);
    scan_kernel<<<1, 1024>>>();
    fill_kernel<<<(NE + 255) / 256, 256>>>(ei);

    // layer 1: 128 -> 128, relu
    gemm_scale_kernel<128, 128, 0><<<gemm_blocks, 256>>>(x, W1, NN);
    agg_kernel<128, 0><<<NN, 64>>>(b1, batch);

    // layer 2: 128 -> 64, relu
    gemm_scale_kernel<128, 64, 1><<<gemm_blocks, 256>>>(nullptr, W2, NN);
    agg_kernel<64, 0><<<NN, 32>>>(b2, batch);

    // layer 3: 64 -> 64, no relu, fused pooling
    gemm_scale_kernel<64, 64, 1><<<gemm_blocks, 256>>>(nullptr, W3, NN);
    agg_kernel<64, 2><<<NN, 32>>>(b3, batch);

    final_kernel<<<(NG + 7) / 8, 256>>>(Wfc, bfc, out);
}

// round 9
// speedup vs baseline: 1.2951x; 1.0570x over previous
#include <cuda_runtime.h>
#include <cuda_fp16.h>
#include <math.h>
#include <stdint.h>

// Problem constants
#define NN 50000
#define NE 800000
#define NF 128
#define NH 128
#define NH2 64
#define NG 512

#define GEMM_BLOCKS ((NN + 127) / 128)          // 391
#define FILL_BLOCKS ((NE + 255) / 256)          // 3125

// ---------------- scratch (static device globals; no allocation) -------------
__device__ __half d_g[(size_t)NN * NF]; // dinv-scaled projected features (fp16)
__device__ float  d_h[(size_t)NN * NF]; // activations (fp32)
__device__ float  d_dinv[NN];
__device__ int    d_cnt[NN];
__device__ int    d_rowptr[NN + 1];
__device__ int    d_cursor[NN];
__device__ int    d_col[NE];
__device__ float  d_pool[NG * NH2];
__device__ int    d_gcnt[NG];

// ---------------- init ------------------------------------------------------
__global__ void init_kernel() {
    int i = blockIdx.x * blockDim.x + threadIdx.x;
    if (i < NN) d_cnt[i] = 0;
    if (i < NG * NH2) d_pool[i] = 0.0f;
    if (i < NG) d_gcnt[i] = 0;
}

// ---------------- degree count (real edges only; self-loop is +1 implicit) --
__global__ void count_kernel(const int* __restrict__ ei) {
    int e = blockIdx.x * blockDim.x + threadIdx.x;
    if (e < NE) {
        int dst = ei[NE + e];
        atomicAdd(&d_cnt[dst], 1);
    }
}

// ---------------- single-block scan: rowptr/cursor/dinv ----------------------
__global__ void scan_kernel() {
    __shared__ int warp_sums[32];
    __shared__ int s_carry;
    int tid = threadIdx.x, lane = tid & 31, wid = tid >> 5;
    if (tid == 0) s_carry = 0;
    __syncthreads();
    for (int base = 0; base < NN; base += 1024) {
        int i = base + tid;
        int v = (i < NN) ? d_cnt[i] : 0;
        int x = v;
        #pragma unroll
        for (int o = 1; o < 32; o <<= 1) {
            int t = __shfl_up_sync(0xFFFFFFFFu, x, o);
            if (lane >= o) x += t;
        }
        if (lane == 31) warp_sums[wid] = x;
        __syncthreads();
        if (wid == 0) {
            int w = warp_sums[lane];
            #pragma unroll
            for (int o = 1; o < 32; o <<= 1) {
                int t = __shfl_up_sync(0xFFFFFFFFu, w, o);
                if (lane >= o) w += t;
            }
            warp_sums[lane] = w;
        }
        __syncthreads();
        int warp_prefix = (wid > 0) ? warp_sums[wid - 1] : 0;
        int incl = s_carry + warp_prefix + x;
        int excl = incl - v;
        if (i < NN) {
            d_rowptr[i] = excl;
            d_cursor[i] = excl;
            d_dinv[i]   = rsqrtf((float)(v + 1));  // deg includes self-loop, >= 1
        }
        __syncthreads();
        if (tid == 1023) s_carry = incl;
        __syncthreads();
    }
    if (threadIdx.x == 0) d_rowptr[NN] = s_carry;
}

// ---------------- GEMM body: d_g = half( dinv[row] * (A @ W) ) ---------------
// BM=128, BK=8, 256 threads, per-thread 8 x (N/16). bid = logical block index.
template <int K, int N, int SRC>   // SRC 0: A = param (x), 1: A = d_h
__device__ __forceinline__ void gemm_body(int bid, const float* __restrict__ Aparam,
                                          const float* __restrict__ W, int M) {
    constexpr int TN = N / 16;
    __shared__ float As[8][128];
    __shared__ float Ws[8][N];
    const float* __restrict__ A = (SRC == 0) ? Aparam : d_h;

    int tid = threadIdx.x;
    int m0 = bid * 128;
    int ty = tid >> 4, tx = tid & 15;
    int mb = ty * 8, nb = tx * TN;

    float acc[8][TN];
    #pragma unroll
    for (int i = 0; i < 8; i++)
        #pragma unroll
        for (int j = 0; j < TN; j++) acc[i][j] = 0.0f;

    int arow = tid >> 1;
    int ac = (tid & 1) * 4;
    bool aok = (m0 + arow) < M;
    const float* Ap = A + (size_t)(m0 + arow) * K + ac;

    for (int k0 = 0; k0 < K; k0 += 8) {
        float4 av = aok ? *(const float4*)(Ap + k0) : make_float4(0.f, 0.f, 0.f, 0.f);
        float4 wv = make_float4(0.f, 0.f, 0.f, 0.f);
        int wrow, wc;
        if (N == 128) {
            wrow = tid >> 5; wc = (tid & 31) * 4;
            wv = *(const float4*)&W[(k0 + wrow) * N + wc];
        } else {
            wrow = tid >> 4; wc = (tid & 15) * 4;
            if (tid < 128) wv = *(const float4*)&W[(k0 + wrow) * N + wc];
        }
        __syncthreads();
        As[ac + 0][arow] = av.x;
        As[ac + 1][arow] = av.y;
        As[ac + 2][arow] = av.z;
        As[ac + 3][arow] = av.w;
        if (N == 128 || tid < 128) *(float4*)&Ws[wrow][wc] = wv;
        __syncthreads();
        #pragma unroll
        for (int k = 0; k < 8; k++) {
            float a0[8];
            *(float4*)(a0)     = *(float4*)&As[k][mb];
            *(float4*)(a0 + 4) = *(float4*)&As[k][mb + 4];
            float b0[TN];
            #pragma unroll
            for (int j4 = 0; j4 < TN; j4 += 4)
                *(float4*)(b0 + j4) = *(float4*)&Ws[k][nb + j4];
            #pragma unroll
            for (int i = 0; i < 8; i++)
                #pragma unroll
                for (int j = 0; j < TN; j++)
                    acc[i][j] = fmaf(a0[i], b0[j], acc[i][j]);
        }
    }

    #pragma unroll
    for (int i = 0; i < 8; i++) {
        int row = m0 + mb + i;
        if (row < M) {
            float s = d_dinv[row];
            #pragma unroll
            for (int j4 = 0; j4 < TN; j4 += 4) {
                __half2 h0 = __floats2half2_rn(acc[i][j4 + 0] * s, acc[i][j4 + 1] * s);
                __half2 h1 = __floats2half2_rn(acc[i][j4 + 2] * s, acc[i][j4 + 3] * s);
                __half2* p = (__half2*)&d_g[(size_t)row * N + nb + j4];
                p[0] = h0;
                p[1] = h1;
            }
        }
    }
}

template <int K, int N, int SRC>
__global__ void gemm_scale_kernel(const float* __restrict__ Aparam,
                                  const float* __restrict__ W, int M) {
    gemm_body<K, N, SRC>(blockIdx.x, Aparam, W, M);
}

// ---------------- fused: gemm1 (blocks 0..390) + CSR fill (rest) -------------
// fill needs only scan (cursor); gemm1 needs only scan (dinv) + x/W1.
// They write disjoint buffers (d_g vs d_col); agg1 consumes both afterwards.
__global__ void gemm1_fill_kernel(const float* __restrict__ x,
                                  const float* __restrict__ W1,
                                  const int* __restrict__ ei) {
    if (blockIdx.x < GEMM_BLOCKS) {
        gemm_body<128, 128, 0>(blockIdx.x, x, W1, NN);
    } else {
        int e = (blockIdx.x - GEMM_BLOCKS) * blockDim.x + threadIdx.x;
        if (e < NE) {
            int s = ei[e];
            int d = ei[NE + e];
            int p = atomicAdd(&d_cursor[d], 1);
            d_col[p] = s;
        }
    }
}

// ---------------- aggregation: out[i] = act(dinv[i]*(self + sum g[src]) + b) -
// block per node, F/2 threads; each thread owns 2 features via __half2.
// cols staged through smem (coalesced), gather loop unrolled 8 (MLP=8).
// MODE 0: relu -> d_h ;  MODE 2: no relu, fused pooling atomics
template <int F, int MODE>
__global__ void agg_kernel(const float* __restrict__ bias,
                           const int* __restrict__ batch) {
    constexpr int T = F / 2;   // threads per block
    __shared__ int scol[T];
    int i = blockIdx.x;
    int f = threadIdx.x;       // 0..T-1, owns features 2f, 2f+1
    const __half2* __restrict__ g2 = (const __half2*)d_g;

    __half2 h = g2[(size_t)i * T + f];          // self-loop term
    float2 acc;
    acc.x = __low2float(h);
    acc.y = __high2float(h);

    int s = d_rowptr[i], e = d_rowptr[i + 1];
    for (int base = s; base < e; base += T) {
        int n = min(T, e - base);
        __syncthreads();
        if (f < n) scol[f] = d_col[base + f];
        __syncthreads();
        int k = 0;
        for (; k + 8 <= n; k += 8) {
            #pragma unroll
            for (int j = 0; j < 8; j++) {
                int c = scol[k + j];
                __half2 v = g2[(size_t)c * T + f];
                acc.x += __low2float(v);
                acc.y += __high2float(v);
            }
        }
        for (; k < n; k++) {
            int c = scol[k];
            __half2 v = g2[(size_t)c * T + f];
            acc.x += __low2float(v);
            acc.y += __high2float(v);
        }
    }

    float di = d_dinv[i];
    float2 b2 = ((const float2*)bias)[f];
    float rx = fmaf(di, acc.x, b2.x);
    float ry = fmaf(di, acc.y, b2.y);
    if (MODE == 0) {
        float2 r;
        r.x = fmaxf(rx, 0.0f);
        r.y = fmaxf(ry, 0.0f);
        ((float2*)d_h)[(size_t)i * T + f] = r;
    } else {
        int b = batch[i];
        atomicAdd(&d_pool[b * NH2 + 2 * f + 0], rx);
        atomicAdd(&d_pool[b * NH2 + 2 * f + 1], ry);
        if (f == 0) atomicAdd(&d_gcnt[b], 1);
    }
}

// ---------------- final: sigmoid(mean) @ Wfc + bfc ---------------------------
__global__ void final_kernel(const float* __restrict__ Wfc,
                             const float* __restrict__ bfc,
                             float* __restrict__ out) {
    int gidx = blockIdx.x * (blockDim.x >> 5) + (threadIdx.x >> 5);
    int lane = threadIdx.x & 31;
    if (gidx >= NG) return;
    float cnt = fmaxf((float)d_gcnt[gidx], 1.0f);
    float s0 = d_pool[gidx * NH2 + lane];
    float s1 = d_pool[gidx * NH2 + 32 + lane];
    float z0 = 1.0f / (1.0f + expf(-s0 / cnt));
    float z1 = 1.0f / (1.0f + expf(-s1 / cnt));
    float p = z0 * Wfc[lane] + z1 * Wfc[lane + 32];
    #pragma unroll
    for (int o = 16; o > 0; o >>= 1) p += __shfl_down_sync(0xFFFFFFFFu, p, o);
    if (lane == 0) out[gidx] = p + bfc[0];
}

// ---------------- launch -----------------------------------------------------
extern "C" void kernel_launch(void* const* d_in, const int* in_sizes, int n_in,
                              void* d_out, int out_size) {
    const float* x     = (const float*)d_in[0];
    const int*   ei    = (const int*)d_in[1];
    const int*   batch = (const int*)d_in[2];
    const float* W1    = (const float*)d_in[3];
    const float* b1    = (const float*)d_in[4];
    const float* W2    = (const float*)d_in[5];
    const float* b2    = (const float*)d_in[6];
    const float* W3    = (const float*)d_in[7];
    const float* b3    = (const float*)d_in[8];
    const float* Wfc   = (const float*)d_in[9];
    const float* bfc   = (const float*)d_in[10];
    float* out = (float*)d_out;

    init_kernel<<<(NN + 255) / 256, 256>>>();
    count_kernel<<<(NE + 255) / 256, 256>>>(ei);
    scan_kernel<<<1, 1024>>>();

    // layer 1 GEMM fused with CSR fill (independent given scan)
    gemm1_fill_kernel<<<GEMM_BLOCKS + FILL_BLOCKS, 256>>>(x, W1, ei);
    agg_kernel<128, 0><<<NN, 64>>>(b1, batch);

    // layer 2: 128 -> 64, relu
    gemm_scale_kernel<128, 64, 1><<<GEMM_BLOCKS, 256>>>(nullptr, W2, NN);
    agg_kernel<64, 0><<<NN, 32>>>(b2, batch);

    // layer 3: 64 -> 64, no relu, fused pooling
    gemm_scale_kernel<64, 64, 1><<<GEMM_BLOCKS, 256>>>(nullptr, W3, NN);
    agg_kernel<64, 2><<<NN, 32>>>(b3, batch);

    final_kernel<<<(NG + 7) / 8, 256>>>(Wfc, bfc, out);
}

// round 10
// speedup vs baseline: 1.3680x; 1.0563x over previous
#include <cuda_runtime.h>
#include <cuda_fp16.h>
#include <mma.h>
#include <math.h>
#include <stdint.h>

using namespace nvcuda;

// Problem constants
#define NN 50000
#define NE 800000
#define NF 128
#define NH 128
#define NH2 64
#define NG 512

#define NROWS_PAD 50048                       // 391 * 128, zero-padded rows
#define GEMM_BLOCKS ((NN + 127) / 128)        // 391
#define EDGE_BLOCKS ((NE + 255) / 256)        // 3125
#define CONV_BLOCKS ((NROWS_PAD * NF) / (256 * 8))  // 3128

// ---------------- scratch (static device globals; no allocation) -------------
__device__ __half d_xh[(size_t)NROWS_PAD * NF];  // x in fp16 (padded rows = 0)
__device__ __half d_h16[(size_t)NROWS_PAD * NF]; // activations fp16 (padded = 0)
__device__ __half d_g[(size_t)NN * NF];          // dinv-scaled projected features
__device__ float  d_dinv[NN];
__device__ int    d_cnt[NN];
__device__ int    d_rowptr[NN + 1];
__device__ int    d_cursor[NN];
__device__ int    d_col[NE];
__device__ float  d_pool[NG * NH2];
__device__ int    d_gcnt[NG];

// ---------------- init ------------------------------------------------------
__global__ void init_kernel() {
    int i = blockIdx.x * blockDim.x + threadIdx.x;
    if (i < NN) d_cnt[i] = 0;
    if (i < NG * NH2) d_pool[i] = 0.0f;
    if (i < NG) d_gcnt[i] = 0;
}

// ---------------- fused: degree count + x -> fp16 convert --------------------
// count branch: 1 edge/thread atomics (latency-bound, rides free).
// convert branch: 8 floats/thread -> uint4 of half2; pad rows set to 0.
__global__ void count_convert_kernel(const int* __restrict__ ei,
                                     const float* __restrict__ x) {
    if (blockIdx.x < EDGE_BLOCKS) {
        int e = blockIdx.x * blockDim.x + threadIdx.x;
        if (e < NE) atomicAdd(&d_cnt[ei[NE + e]], 1);
    } else {
        int t = (blockIdx.x - EDGE_BLOCKS) * blockDim.x + threadIdx.x;
        size_t e0 = (size_t)t * 8;   // NN*NF divisible by 8; grid covers pad exactly
        if (e0 < (size_t)NN * NF) {
            float4 f0 = *(const float4*)&x[e0];
            float4 f1 = *(const float4*)&x[e0 + 4];
            __half2 h[4];
            h[0] = __floats2half2_rn(f0.x, f0.y);
            h[1] = __floats2half2_rn(f0.z, f0.w);
            h[2] = __floats2half2_rn(f1.x, f1.y);
            h[3] = __floats2half2_rn(f1.z, f1.w);
            *(uint4*)&d_xh[e0] = *(uint4*)h;
        } else {
            uint4 z = make_uint4(0, 0, 0, 0);
            *(uint4*)&d_xh[e0] = z;
        }
    }
}

// ---------------- single-block scan: rowptr/cursor/dinv ----------------------
__global__ void scan_kernel() {
    __shared__ int warp_sums[32];
    __shared__ int s_carry;
    int tid = threadIdx.x, lane = tid & 31, wid = tid >> 5;
    if (tid == 0) s_carry = 0;
    __syncthreads();
    for (int base = 0; base < NN; base += 1024) {
        int i = base + tid;
        int v = (i < NN) ? d_cnt[i] : 0;
        int x = v;
        #pragma unroll
        for (int o = 1; o < 32; o <<= 1) {
            int t = __shfl_up_sync(0xFFFFFFFFu, x, o);
            if (lane >= o) x += t;
        }
        if (lane == 31) warp_sums[wid] = x;
        __syncthreads();
        if (wid == 0) {
            int w = warp_sums[lane];
            #pragma unroll
            for (int o = 1; o < 32; o <<= 1) {
                int t = __shfl_up_sync(0xFFFFFFFFu, w, o);
                if (lane >= o) w += t;
            }
            warp_sums[lane] = w;
        }
        __syncthreads();
        int warp_prefix = (wid > 0) ? warp_sums[wid - 1] : 0;
        int incl = s_carry + warp_prefix + x;
        int excl = incl - v;
        if (i < NN) {
            d_rowptr[i] = excl;
            d_cursor[i] = excl;
            d_dinv[i]   = rsqrtf((float)(v + 1));  // deg includes self-loop, >= 1
        }
        __syncthreads();
        if (tid == 1023) s_carry = incl;
        __syncthreads();
    }
    if (threadIdx.x == 0) d_rowptr[NN] = s_carry;
}

// ---------------- wmma fp16 GEMM body: d_g = half(dinv[row] * (A @ W)) -------
// 256 threads = 8 warps; block tile 128 x N; warp = 16-row strip.
// A fp16 in global (padded rows -> safe OOB-free loads); W staged fp16 in smem.
template <int K, int N, int SRC>   // SRC 0: A = d_xh, 1: A = d_h16
__device__ __forceinline__ void gemm_wmma_body(int bid, const float* __restrict__ W) {
    constexpr int NFRAG = N / 16;
    constexpr int KSTEPS = K / 16;
    // union: W tile (mainloop) / epilogue bounce buffers
    __shared__ __align__(16) char raw[(K * N * 2) > (8 * 16 * 24 * 4)
                                      ? (K * N * 2) : (8 * 16 * 24 * 4)];
    __half* Wsh = (__half*)raw;
    const __half* __restrict__ A = (SRC == 0) ? d_xh : d_h16;

    int tid = threadIdx.x, warp = tid >> 5, lane = tid & 31;
    int mrow = bid * 128 + warp * 16;

    // stage W (fp32 -> fp16), float2 -> half2
    for (int i = tid; i < K * N / 2; i += 256) {
        float2 w2 = *(const float2*)&W[i * 2];
        *(__half2*)&Wsh[i * 2] = __floats2half2_rn(w2.x, w2.y);
    }
    __syncthreads();

    wmma::fragment<wmma::accumulator, 16, 16, 16, float> acc[NFRAG];
    #pragma unroll
    for (int nf = 0; nf < NFRAG; nf++) wmma::fill_fragment(acc[nf], 0.0f);

    #pragma unroll
    for (int ks = 0; ks < KSTEPS; ks++) {
        wmma::fragment<wmma::matrix_a, 16, 16, 16, __half, wmma::row_major> a;
        wmma::load_matrix_sync(a, A + (size_t)mrow * K + ks * 16, K);
        #pragma unroll
        for (int nf = 0; nf < NFRAG; nf++) {
            wmma::fragment<wmma::matrix_b, 16, 16, 16, __half, wmma::row_major> b;
            wmma::load_matrix_sync(b, Wsh + ks * 16 * N + nf * 16, N);
            wmma::mma_sync(acc[nf], a, b, acc[nf]);
        }
    }

    // epilogue: bounce frags through smem (reusing W region), scale, fp16 store
    __syncthreads();
    float* Cs = (float*)raw + warp * (16 * 24);
    int r = lane >> 1;
    int c0 = (lane & 1) * 8;
    int row = mrow + r;
    float s = (row < NN) ? d_dinv[row] : 0.0f;
    #pragma unroll
    for (int nf = 0; nf < NFRAG; nf++) {
        wmma::store_matrix_sync(Cs, acc[nf], 24, wmma::mem_row_major);
        __syncwarp();
        if (row < NN) {
            float v[8];
            #pragma unroll
            for (int j = 0; j < 8; j++) v[j] = Cs[r * 24 + c0 + j] * s;
            __half2 h[4];
            #pragma unroll
            for (int j = 0; j < 4; j++)
                h[j] = __floats2half2_rn(v[2 * j], v[2 * j + 1]);
            *(uint4*)&d_g[(size_t)row * N + nf * 16 + c0] = *(uint4*)h;
        }
        __syncwarp();
    }
}

template <int K, int N, int SRC>
__global__ void gemm_wmma_kernel(const float* __restrict__ W) {
    gemm_wmma_body<K, N, SRC>(blockIdx.x, W);
}

// ---------------- fused: gemm1 (blocks 0..390) + CSR fill (rest) -------------
__global__ void gemm1_fill_kernel(const float* __restrict__ W1,
                                  const int* __restrict__ ei) {
    if (blockIdx.x < GEMM_BLOCKS) {
        gemm_wmma_body<128, 128, 0>(blockIdx.x, W1);
    } else {
        int e = (blockIdx.x - GEMM_BLOCKS) * blockDim.x + threadIdx.x;
        if (e < NE) {
            int s = ei[e];
            int d = ei[NE + e];
            int p = atomicAdd(&d_cursor[d], 1);
            d_col[p] = s;
        }
    }
}

// ---------------- aggregation: out[i] = act(dinv[i]*(self + sum g[src]) + b) -
// block per node, F/2 threads; each thread owns 2 features via __half2.
// cols staged through smem (coalesced), gather loop unrolled 8 (MLP=8).
// MODE 0: relu -> d_h16 (fp16) ;  MODE 2: no relu, fused pooling atomics
template <int F, int MODE>
__global__ void agg_kernel(const float* __restrict__ bias,
                           const int* __restrict__ batch) {
    constexpr int T = F / 2;   // threads per block
    __shared__ int scol[T];
    int i = blockIdx.x;
    int f = threadIdx.x;       // 0..T-1, owns features 2f, 2f+1
    const __half2* __restrict__ g2 = (const __half2*)d_g;

    __half2 h = g2[(size_t)i * T + f];          // self-loop term
    float2 acc;
    acc.x = __low2float(h);
    acc.y = __high2float(h);

    int s = d_rowptr[i], e = d_rowptr[i + 1];
    for (int base = s; base < e; base += T) {
        int n = min(T, e - base);
        __syncthreads();
        if (f < n) scol[f] = d_col[base + f];
        __syncthreads();
        int k = 0;
        for (; k + 8 <= n; k += 8) {
            #pragma unroll
            for (int j = 0; j < 8; j++) {
                int c = scol[k + j];
                __half2 v = g2[(size_t)c * T + f];
                acc.x += __low2float(v);
                acc.y += __high2float(v);
            }
        }
        for (; k < n; k++) {
            int c = scol[k];
            __half2 v = g2[(size_t)c * T + f];
            acc.x += __low2float(v);
            acc.y += __high2float(v);
        }
    }

    float di = d_dinv[i];
    float2 b2 = ((const float2*)bias)[f];
    float rx = fmaf(di, acc.x, b2.x);
    float ry = fmaf(di, acc.y, b2.y);
    if (MODE == 0) {
        ((__half2*)d_h16)[(size_t)i * T + f] =
            __floats2half2_rn(fmaxf(rx, 0.0f), fmaxf(ry, 0.0f));
    } else {
        int b = batch[i];
        atomicAdd(&d_pool[b * NH2 + 2 * f + 0], rx);
        atomicAdd(&d_pool[b * NH2 + 2 * f + 1], ry);
        if (f == 0) atomicAdd(&d_gcnt[b], 1);
    }
}

// ---------------- final: sigmoid(mean) @ Wfc + bfc ---------------------------
__global__ void final_kernel(const float* __restrict__ Wfc,
                             const float* __restrict__ bfc,
                             float* __restrict__ out) {
    int gidx = blockIdx.x * (blockDim.x >> 5) + (threadIdx.x >> 5);
    int lane = threadIdx.x & 31;
    if (gidx >= NG) return;
    float cnt = fmaxf((float)d_gcnt[gidx], 1.0f);
    float s0 = d_pool[gidx * NH2 + lane];
    float s1 = d_pool[gidx * NH2 + 32 + lane];
    float z0 = 1.0f / (1.0f + expf(-s0 / cnt));
    float z1 = 1.0f / (1.0f + expf(-s1 / cnt));
    float p = z0 * Wfc[lane] + z1 * Wfc[lane + 32];
    #pragma unroll
    for (int o = 16; o > 0; o >>= 1) p += __shfl_down_sync(0xFFFFFFFFu, p, o);
    if (lane == 0) out[gidx] = p + bfc[0];
}

// ---------------- launch -----------------------------------------------------
extern "C" void kernel_launch(void* const* d_in, const int* in_sizes, int n_in,
                              void* d_out, int out_size) {
    const float* x     = (const float*)d_in[0];
    const int*   ei    = (const int*)d_in[1];
    const int*   batch = (const int*)d_in[2];
    const float* W1    = (const float*)d_in[3];
    const float* b1    = (const float*)d_in[4];
    const float* W2    = (const float*)d_in[5];
    const float* b2    = (const float*)d_in[6];
    const float* W3    = (const float*)d_in[7];
    const float* b3    = (const float*)d_in[8];
    const float* Wfc   = (const float*)d_in[9];
    const float* bfc   = (const float*)d_in[10];
    float* out = (float*)d_out;

    init_kernel<<<(NN + 255) / 256, 256>>>();
    count_convert_kernel<<<EDGE_BLOCKS + CONV_BLOCKS, 256>>>(ei, x);
    scan_kernel<<<1, 1024>>>();

    // layer 1 GEMM (wmma fp16) fused with CSR fill
    gemm1_fill_kernel<<<GEMM_BLOCKS + EDGE_BLOCKS, 256>>>(W1, ei);
    agg_kernel<128, 0><<<NN, 64>>>(b1, batch);

    // layer 2: 128 -> 64, relu
    gemm_wmma_kernel<128, 64, 1><<<GEMM_BLOCKS, 256>>>(W2);
    agg_kernel<64, 0><<<NN, 32>>>(b2, batch);

    // layer 3: 64 -> 64, no relu, fused pooling
    gemm_wmma_kernel<64, 64, 1><<<GEMM_BLOCKS, 256>>>(W3);
    agg_kernel<64, 2><<<NN, 32>>>(b3, batch);

    final_kernel<<<(NG + 7) / 8, 256>>>(Wfc, bfc, out);
}